// round 7
// baseline (speedup 1.0000x reference)
#include <cuda_runtime.h>
#include <cuda_bf16.h>
#include <cstdint>
#include <cstddef>

// Problem dims (fixed by the dataset)
#define M_DIM 8192
#define N_DIM 1536
#define K_DIM 512
#define H_DIM 512
#define KP    (3 * K_DIM)     // packed K' = 1536

// ---------------------------------------------------------------------------
// Device-global scratch (no cudaMalloc allowed)
// ---------------------------------------------------------------------------
__device__ float g_gi[(size_t)M_DIM * N_DIM];
__device__ float g_gh[(size_t)M_DIM * N_DIM];

// Packed split operands: A' = [hi | hi | lo], B' = [hi | lo | hi]
__device__ __nv_bfloat16 g_xp[(size_t)M_DIM * KP];
__device__ __nv_bfloat16 g_hp[(size_t)M_DIM * KP];
__device__ __nv_bfloat16 g_wip[(size_t)N_DIM * KP];
__device__ __nv_bfloat16 g_whp[(size_t)N_DIM * KP];

// ---------------------------------------------------------------------------
// Quantization helpers (exact fp32 semantics, no FMA contraction)
// ---------------------------------------------------------------------------
#define Q27F   134217728.0f
#define IQ27F  7.450580596923828125e-9f    // 2^-27
#define Q31F   2147483648.0f
#define IQ16F  1.52587890625e-5f           // 2^-16
#define S15F   32768.0f
#define I15F   3.0517578125e-5f            // 2^-15
#define S14F   16384.0f
#define I14F   6.103515625e-5f             // 2^-14

__device__ __forceinline__ float qround(float x, float s, float inv) {
    return __fmul_rn(floorf(__fadd_rn(__fmul_rn(x, s), 0.5f)), inv);
}

__device__ __forceinline__ float qsig(float x) {
    float t = floorf(__fadd_rn(__fmul_rn(x, Q27F), 0.5f));
    t = fminf(fmaxf(t, -2147483648.0f), 2147483648.0f);
    float xr = __fmul_rn(t, IQ27F);
    float s  = 1.0f / (1.0f + expf(-xr));
    float q31 = floorf(__fadd_rn(__fmul_rn(s, Q31F), 0.5f));
    float q15 = floorf(__fadd_rn(__fmul_rn(q31, IQ16F), 0.5f));
    return __fmul_rn(q15, I15F);
}

__device__ __forceinline__ float qtanhf_(float x) {
    float t = floorf(__fadd_rn(__fmul_rn(x, Q27F), 0.5f));
    t = fminf(fmaxf(t, -2147483648.0f), 2147483648.0f);
    float xr = __fmul_rn(t, IQ27F);
    float s  = tanhf(xr);
    float q31 = floorf(__fadd_rn(__fmul_rn(s, Q31F), 0.5f));
    float q15 = floorf(__fadd_rn(__fmul_rn(q31, IQ16F), 0.5f));
    return __fmul_rn(q15, I15F);
}

// ---------------------------------------------------------------------------
// PTX helpers (baseline sm_103-safe: mma.sync / ldmatrix / cp.async only)
// ---------------------------------------------------------------------------
__device__ __forceinline__ uint32_t smem_u32(const void* p) {
    uint32_t a;
    asm("{ .reg .u64 t; cvta.to.shared.u64 t, %1; cvt.u32.u64 %0, t; }" : "=r"(a) : "l"(p));
    return a;
}

__device__ __forceinline__ void cp16(uint32_t dst, const void* src) {
    asm volatile("cp.async.cg.shared.global [%0], [%1], 16;" :: "r"(dst), "l"(src) : "memory");
}

__device__ __forceinline__ void ldmatrix_x4(uint32_t& r0, uint32_t& r1,
                                            uint32_t& r2, uint32_t& r3,
                                            uint32_t addr) {
    asm volatile("ldmatrix.sync.aligned.m8n8.x4.shared.b16 {%0,%1,%2,%3}, [%4];"
                 : "=r"(r0), "=r"(r1), "=r"(r2), "=r"(r3) : "r"(addr));
}

__device__ __forceinline__ void mma_bf16(float& d0, float& d1, float& d2, float& d3,
                                         uint32_t a0, uint32_t a1, uint32_t a2, uint32_t a3,
                                         uint32_t b0, uint32_t b1) {
    asm volatile(
        "mma.sync.aligned.m16n8k16.row.col.f32.bf16.bf16.f32 "
        "{%0,%1,%2,%3}, {%4,%5,%6,%7}, {%8,%9}, {%0,%1,%2,%3};"
        : "+f"(d0), "+f"(d1), "+f"(d2), "+f"(d3)
        : "r"(a0), "r"(a1), "r"(a2), "r"(a3), "r"(b0), "r"(b1));
}

// ---------------------------------------------------------------------------
// fp32 -> packed bf16 hi/lo split, float4-vectorized (4 elems / thread).
// mode 0 (activations A'): [hi | hi | lo]
// mode 1 (weights     B'): [hi | lo | hi]
// ---------------------------------------------------------------------------
__global__ __launch_bounds__(256)
void split_pack(const float* __restrict__ src, __nv_bfloat16* __restrict__ dst,
                int rows, int mode)
{
    int i4 = blockIdx.x * blockDim.x + threadIdx.x;
    if (i4 >= rows * (K_DIM / 4)) return;
    int m = i4 >> 7;             // / (K_DIM/4)
    int k = (i4 & 127) << 2;
    float4 v = *reinterpret_cast<const float4*>(src + (size_t)m * K_DIM + k);
    float vv[4] = {v.x, v.y, v.z, v.w};
    __nv_bfloat16 hi[4], lo[4];
    #pragma unroll
    for (int j = 0; j < 4; j++) {
        hi[j] = __float2bfloat16_rn(vv[j]);
        lo[j] = __float2bfloat16_rn(vv[j] - __bfloat162float(hi[j]));
    }
    __nv_bfloat16* d = dst + (size_t)m * KP + k;
    uint2 hip = {((uint32_t)__bfloat16_as_ushort(hi[1]) << 16) | __bfloat16_as_ushort(hi[0]),
                 ((uint32_t)__bfloat16_as_ushort(hi[3]) << 16) | __bfloat16_as_ushort(hi[2])};
    uint2 lop = {((uint32_t)__bfloat16_as_ushort(lo[1]) << 16) | __bfloat16_as_ushort(lo[0]),
                 ((uint32_t)__bfloat16_as_ushort(lo[3]) << 16) | __bfloat16_as_ushort(lo[2])};
    *reinterpret_cast<uint2*>(d)              = hip;
    *reinterpret_cast<uint2*>(d + K_DIM)      = mode ? lop : hip;
    *reinterpret_cast<uint2*>(d + 2 * K_DIM)  = mode ? hip : lop;
}

// ---------------------------------------------------------------------------
// GEMM via mma.sync (bf16, fp32 accum):
//   C[m,n] = q14( sum_{k'} A'[m,k'] * B'[n,k'] + bias[n] )
// Tile 128x128, BK=64, 256 threads (8 warps, each 32x64),
// 4-stage cp.async pipeline, ONE __syncthreads per chunk.
// grid = (12, 64, 2); z selects (x,Wih,gi,bih) vs (h,Whh,gh,bhh).
// ---------------------------------------------------------------------------
#define TILE_M 128
#define TILE_N 128
#define BK 64
#define NCH (KP / BK)          // 24
#define STAGES 4
#define ROWSTRIDE 72           // bf16 elems per smem row (128B data + 16B pad)
#define STAGE_ELEMS (TILE_M * ROWSTRIDE)          // per operand per stage
#define SM_A_OFF 0
#define SM_B_OFF (STAGES * STAGE_ELEMS)
#define SM_BIAS_OFF (2 * STAGES * STAGE_ELEMS)    // in bf16 elems (float area)
#define GSMEM_BYTES (SM_BIAS_OFF * 2 + TILE_N * 4)   // 147456 + 512

__device__ __forceinline__ void load_chunk(uint32_t as_base, uint32_t bs_base,
                                           const __nv_bfloat16* __restrict__ Ag,
                                           const __nv_bfloat16* __restrict__ Bg,
                                           int tid)
{
    // per operand: 128 rows x 8 segs(16B) = 1024 cp16; 256 threads -> 4 each
    #pragma unroll
    for (int o = 0; o < 4; o++) {
        int lin = tid + o * 256;
        int row = lin >> 3, seg = lin & 7;
        uint32_t off = ((uint32_t)row * ROWSTRIDE + (uint32_t)seg * 8) * 2;
        cp16(as_base + off, Ag + (size_t)row * KP + seg * 8);
        cp16(bs_base + off, Bg + (size_t)row * KP + seg * 8);
    }
}

__global__ __launch_bounds__(256)
void gemm_mma(const float* __restrict__ bias_i, const float* __restrict__ bias_h)
{
    extern __shared__ __align__(16) __nv_bfloat16 sm[];
    float* sb_bias = (float*)(sm + SM_BIAS_OFF);

    const int tid = threadIdx.x;
    const int wid = tid >> 5, lane = tid & 31;
    const int n0 = blockIdx.x * TILE_N;
    const int m0 = blockIdx.y * TILE_M;
    const int z  = blockIdx.z;

    const __nv_bfloat16* __restrict__ A = z ? g_hp  : g_xp;
    const __nv_bfloat16* __restrict__ B = z ? g_whp : g_wip;
    const float* __restrict__ bias = z ? bias_h : bias_i;
    float* __restrict__ C = z ? g_gh : g_gi;

    if (tid < TILE_N) sb_bias[tid] = bias[n0 + tid];

    const uint32_t smb = smem_u32(sm);

    // warp tile: 4x2 grid of warps -> each warp 32 (m) x 64 (n)
    const int wm = (wid & 3) * 32;
    const int wn = (wid >> 2) * 64;
    const int g  = lane >> 2;
    const int tq = lane & 3;

    float d[2][8][4];
    #pragma unroll
    for (int a = 0; a < 2; a++)
        #pragma unroll
        for (int b = 0; b < 8; b++)
            #pragma unroll
            for (int c = 0; c < 4; c++) d[a][b][c] = 0.0f;

    // ldmatrix lane mappings
    const int lm_row = (lane & 15);
    const int lm_hi  = (lane >> 4) & 1;
    const int lb_row = ((lane >> 4) & 1) * 8 + (lane & 7);
    const int lb_seg = (lane >> 3) & 1;

    const __nv_bfloat16* Ag0 = A + (size_t)m0 * KP;
    const __nv_bfloat16* Bg0 = B + (size_t)n0 * KP;

    // Prologue: chunks 0..2 into stages 0..2
    #pragma unroll
    for (int c = 0; c < STAGES - 1; c++) {
        load_chunk(smb + (SM_A_OFF + c * STAGE_ELEMS) * 2,
                   smb + (SM_B_OFF + c * STAGE_ELEMS) * 2,
                   Ag0 + c * BK, Bg0 + c * BK, tid);
        asm volatile("cp.async.commit_group;" ::: "memory");
    }

    for (int c = 0; c < NCH; c++) {
        const int s = c & (STAGES - 1);

        if (c < NCH - 2)       asm volatile("cp.async.wait_group 2;" ::: "memory");
        else if (c == NCH - 2) asm volatile("cp.async.wait_group 1;" ::: "memory");
        else                   asm volatile("cp.async.wait_group 0;" ::: "memory");
        __syncthreads();

        // Prefetch chunk c+3 into stage (c+3)%4 (consumed at iter c-1;
        // the sync above ordered that compute before this write).
        if (c + STAGES - 1 < NCH) {
            const int sp = (c + STAGES - 1) & (STAGES - 1);
            load_chunk(smb + (SM_A_OFF + sp * STAGE_ELEMS) * 2,
                       smb + (SM_B_OFF + sp * STAGE_ELEMS) * 2,
                       Ag0 + (c + STAGES - 1) * BK, Bg0 + (c + STAGES - 1) * BK, tid);
            asm volatile("cp.async.commit_group;" ::: "memory");
        }

        const uint32_t as = smb + (SM_A_OFF + s * STAGE_ELEMS) * 2;
        const uint32_t bs = smb + (SM_B_OFF + s * STAGE_ELEMS) * 2;

        #pragma unroll
        for (int ks = 0; ks < BK / 16; ks++) {
            uint32_t aF[2][4];
            #pragma unroll
            for (int mt = 0; mt < 2; mt++) {
                uint32_t addr = as + (((uint32_t)(wm + mt * 16 + lm_row) * ROWSTRIDE)
                                      + ks * 16 + lm_hi * 8) * 2;
                ldmatrix_x4(aF[mt][0], aF[mt][1], aF[mt][2], aF[mt][3], addr);
            }
            uint32_t bF[8][2];
            #pragma unroll
            for (int nt = 0; nt < 4; nt++) {
                uint32_t r0, r1, r2, r3;
                uint32_t addr = bs + (((uint32_t)(wn + nt * 16 + lb_row) * ROWSTRIDE)
                                      + ks * 16 + lb_seg * 8) * 2;
                ldmatrix_x4(r0, r1, r2, r3, addr);
                bF[nt * 2 + 0][0] = r0; bF[nt * 2 + 0][1] = r1;
                bF[nt * 2 + 1][0] = r2; bF[nt * 2 + 1][1] = r3;
            }
            #pragma unroll
            for (int mt = 0; mt < 2; mt++)
                #pragma unroll
                for (int nt = 0; nt < 8; nt++)
                    mma_bf16(d[mt][nt][0], d[mt][nt][1], d[mt][nt][2], d[mt][nt][3],
                             aF[mt][0], aF[mt][1], aF[mt][2], aF[mt][3],
                             bF[nt][0], bF[nt][1]);
        }
    }

    // Epilogue: +bias, q14, store.
    #pragma unroll
    for (int mt = 0; mt < 2; mt++) {
        int r0 = m0 + wm + mt * 16 + g;
        int r1 = r0 + 8;
        #pragma unroll
        for (int nt = 0; nt < 8; nt++) {
            int cl = wn + nt * 8 + tq * 2;
            float b0 = sb_bias[cl], b1 = sb_bias[cl + 1];
            float2 o0, o1;
            o0.x = qround(d[mt][nt][0] + b0, S14F, I14F);
            o0.y = qround(d[mt][nt][1] + b1, S14F, I14F);
            o1.x = qround(d[mt][nt][2] + b0, S14F, I14F);
            o1.y = qround(d[mt][nt][3] + b1, S14F, I14F);
            *reinterpret_cast<float2*>(C + (size_t)r0 * N_DIM + n0 + cl) = o0;
            *reinterpret_cast<float2*>(C + (size_t)r1 * N_DIM + n0 + cl) = o1;
        }
    }
}

// ---------------------------------------------------------------------------
// Fused gate epilogue over [B, H], float4-vectorized.
// ---------------------------------------------------------------------------
__global__ __launch_bounds__(256)
void qgru_epilogue(const float* __restrict__ hidden, float* __restrict__ out)
{
    int idx = blockIdx.x * blockDim.x + threadIdx.x;
    if (idx >= (M_DIM * H_DIM) / 4) return;
    int b = idx >> 7;
    int h = (idx & 127) << 2;

    const float* gib = g_gi + (size_t)b * N_DIM;
    const float* ghb = g_gh + (size_t)b * N_DIM;

    float4 ir = *reinterpret_cast<const float4*>(gib + h);
    float4 ii = *reinterpret_cast<const float4*>(gib + h + H_DIM);
    float4 in_ = *reinterpret_cast<const float4*>(gib + h + 2 * H_DIM);
    float4 hr = *reinterpret_cast<const float4*>(ghb + h);
    float4 hi = *reinterpret_cast<const float4*>(ghb + h + H_DIM);
    float4 hn = *reinterpret_cast<const float4*>(ghb + h + 2 * H_DIM);
    float4 hd = *reinterpret_cast<const float4*>(hidden + (size_t)b * H_DIM + h);

    float irA[4] = {ir.x, ir.y, ir.z, ir.w};
    float iiA[4] = {ii.x, ii.y, ii.z, ii.w};
    float inA[4] = {in_.x, in_.y, in_.z, in_.w};
    float hrA[4] = {hr.x, hr.y, hr.z, hr.w};
    float hiA[4] = {hi.x, hi.y, hi.z, hi.w};
    float hnA[4] = {hn.x, hn.y, hn.z, hn.w};
    float hdA[4] = {hd.x, hd.y, hd.z, hd.w};
    float res[4];

    #pragma unroll
    for (int l = 0; l < 4; l++) {
        float rg  = qsig(__fadd_rn(irA[l], hrA[l]));
        float ig  = qsig(__fadd_rn(iiA[l], hiA[l]));
        float hnq = qround(hnA[l], Q27F, IQ27F);
        float rh  = qround(__fmul_rn(rg, hnq), S15F, I15F);
        float ng  = qtanhf_(__fadd_rn(rh, inA[l]));
        float nh  = qround(hdA[l], S15F, I15F);
        res[l] = __fadd_rn(ng, __fmul_rn(ig, __fsub_rn(nh, ng)));
    }

    float4 o = {res[0], res[1], res[2], res[3]};
    *reinterpret_cast<float4*>(out + (size_t)b * H_DIM + h) = o;
}

// ---------------------------------------------------------------------------
extern "C" void kernel_launch(void* const* d_in, const int* in_sizes, int n_in,
                              void* d_out, int out_size)
{
    const float* x   = (const float*)d_in[0];
    const float* h   = (const float*)d_in[1];
    const float* wih = (const float*)d_in[2];
    const float* whh = (const float*)d_in[3];
    const float* bih = (const float*)d_in[4];
    const float* bhh = (const float*)d_in[5];
    float* out = (float*)d_out;

    cudaFuncSetAttribute(gemm_mma, cudaFuncAttributeMaxDynamicSharedMemorySize,
                         GSMEM_BYTES);

    __nv_bfloat16 *xp, *hp, *wip, *whp;
    cudaGetSymbolAddress((void**)&xp,  g_xp);
    cudaGetSymbolAddress((void**)&hp,  g_hp);
    cudaGetSymbolAddress((void**)&wip, g_wip);
    cudaGetSymbolAddress((void**)&whp, g_whp);

    const int nA4 = M_DIM * (K_DIM / 4);
    const int nW4 = N_DIM * (K_DIM / 4);
    split_pack<<<(nA4 + 255) / 256, 256>>>(x,   xp,  M_DIM, 0);
    split_pack<<<(nA4 + 255) / 256, 256>>>(h,   hp,  M_DIM, 0);
    split_pack<<<(nW4 + 255) / 256, 256>>>(wih, wip, N_DIM, 1);
    split_pack<<<(nW4 + 255) / 256, 256>>>(whh, whp, N_DIM, 1);

    dim3 grid(N_DIM / TILE_N, M_DIM / TILE_M, 2);   // (12, 64, 2)
    gemm_mma<<<grid, 256, GSMEM_BYTES>>>(bih, bhh);

    int total = (M_DIM * H_DIM) / 4;
    qgru_epilogue<<<(total + 255) / 256, 256>>>(h, out);
}

// round 11
// speedup vs baseline: 1.6755x; 1.6755x over previous
#include <cuda_runtime.h>
#include <cuda_bf16.h>
#include <cstdint>
#include <cstddef>

// Problem dims (fixed by the dataset)
#define M_DIM 8192
#define N_DIM 1536
#define K_DIM 512
#define H_DIM 512
#define KP    (3 * K_DIM)     // packed K' = 1536

// ---------------------------------------------------------------------------
// Device-global scratch (no cudaMalloc allowed)
// ---------------------------------------------------------------------------
__device__ float g_gi[(size_t)M_DIM * N_DIM];
__device__ float g_gh[(size_t)M_DIM * N_DIM];

// Packed split operands: A' = [hi | hi | lo], B' = [hi | lo | hi]
__device__ __nv_bfloat16 g_xp[(size_t)M_DIM * KP];
__device__ __nv_bfloat16 g_hp[(size_t)M_DIM * KP];
__device__ __nv_bfloat16 g_wip[(size_t)N_DIM * KP];
__device__ __nv_bfloat16 g_whp[(size_t)N_DIM * KP];

// ---------------------------------------------------------------------------
// Quantization helpers (exact fp32 semantics, no FMA contraction)
// ---------------------------------------------------------------------------
#define Q27F   134217728.0f
#define IQ27F  7.450580596923828125e-9f    // 2^-27
#define Q31F   2147483648.0f
#define IQ16F  1.52587890625e-5f           // 2^-16
#define S15F   32768.0f
#define I15F   3.0517578125e-5f            // 2^-15
#define S14F   16384.0f
#define I14F   6.103515625e-5f             // 2^-14

__device__ __forceinline__ float qround(float x, float s, float inv) {
    return __fmul_rn(floorf(__fadd_rn(__fmul_rn(x, s), 0.5f)), inv);
}

__device__ __forceinline__ float qsig(float x) {
    float t = floorf(__fadd_rn(__fmul_rn(x, Q27F), 0.5f));
    t = fminf(fmaxf(t, -2147483648.0f), 2147483648.0f);
    float xr = __fmul_rn(t, IQ27F);
    float s  = 1.0f / (1.0f + expf(-xr));
    float q31 = floorf(__fadd_rn(__fmul_rn(s, Q31F), 0.5f));
    float q15 = floorf(__fadd_rn(__fmul_rn(q31, IQ16F), 0.5f));
    return __fmul_rn(q15, I15F);
}

__device__ __forceinline__ float qtanhf_(float x) {
    float t = floorf(__fadd_rn(__fmul_rn(x, Q27F), 0.5f));
    t = fminf(fmaxf(t, -2147483648.0f), 2147483648.0f);
    float xr = __fmul_rn(t, IQ27F);
    float s  = tanhf(xr);
    float q31 = floorf(__fadd_rn(__fmul_rn(s, Q31F), 0.5f));
    float q15 = floorf(__fadd_rn(__fmul_rn(q31, IQ16F), 0.5f));
    return __fmul_rn(q15, I15F);
}

// ---------------------------------------------------------------------------
// PTX helpers (baseline sm_103-safe: mma.sync / ldmatrix / cp.async only)
// ---------------------------------------------------------------------------
__device__ __forceinline__ uint32_t smem_u32(const void* p) {
    uint32_t a;
    asm("{ .reg .u64 t; cvta.to.shared.u64 t, %1; cvt.u32.u64 %0, t; }" : "=r"(a) : "l"(p));
    return a;
}

__device__ __forceinline__ void cp16(uint32_t dst, const void* src) {
    asm volatile("cp.async.cg.shared.global [%0], [%1], 16;" :: "r"(dst), "l"(src) : "memory");
}

__device__ __forceinline__ void ldmatrix_x4(uint32_t& r0, uint32_t& r1,
                                            uint32_t& r2, uint32_t& r3,
                                            uint32_t addr) {
    asm volatile("ldmatrix.sync.aligned.m8n8.x4.shared.b16 {%0,%1,%2,%3}, [%4];"
                 : "=r"(r0), "=r"(r1), "=r"(r2), "=r"(r3) : "r"(addr));
}

__device__ __forceinline__ void mma_bf16(float& d0, float& d1, float& d2, float& d3,
                                         uint32_t a0, uint32_t a1, uint32_t a2, uint32_t a3,
                                         uint32_t b0, uint32_t b1) {
    asm volatile(
        "mma.sync.aligned.m16n8k16.row.col.f32.bf16.bf16.f32 "
        "{%0,%1,%2,%3}, {%4,%5,%6,%7}, {%8,%9}, {%0,%1,%2,%3};"
        : "+f"(d0), "+f"(d1), "+f"(d2), "+f"(d3)
        : "r"(a0), "r"(a1), "r"(a2), "r"(a3), "r"(b0), "r"(b1));
}

// ---------------------------------------------------------------------------
// fp32 -> packed bf16 hi/lo split, float4-vectorized (4 elems / thread).
// mode 0 (activations A'): [hi | hi | lo]
// mode 1 (weights     B'): [hi | lo | hi]
// ---------------------------------------------------------------------------
__global__ __launch_bounds__(256)
void split_pack(const float* __restrict__ src, __nv_bfloat16* __restrict__ dst,
                int rows, int mode)
{
    int i4 = blockIdx.x * blockDim.x + threadIdx.x;
    if (i4 >= rows * (K_DIM / 4)) return;
    int m = i4 >> 7;             // / (K_DIM/4)
    int k = (i4 & 127) << 2;
    float4 v = *reinterpret_cast<const float4*>(src + (size_t)m * K_DIM + k);
    float vv[4] = {v.x, v.y, v.z, v.w};
    __nv_bfloat16 hi[4], lo[4];
    #pragma unroll
    for (int j = 0; j < 4; j++) {
        hi[j] = __float2bfloat16_rn(vv[j]);
        lo[j] = __float2bfloat16_rn(vv[j] - __bfloat162float(hi[j]));
    }
    __nv_bfloat16* d = dst + (size_t)m * KP + k;
    uint2 hip = {((uint32_t)__bfloat16_as_ushort(hi[1]) << 16) | __bfloat16_as_ushort(hi[0]),
                 ((uint32_t)__bfloat16_as_ushort(hi[3]) << 16) | __bfloat16_as_ushort(hi[2])};
    uint2 lop = {((uint32_t)__bfloat16_as_ushort(lo[1]) << 16) | __bfloat16_as_ushort(lo[0]),
                 ((uint32_t)__bfloat16_as_ushort(lo[3]) << 16) | __bfloat16_as_ushort(lo[2])};
    *reinterpret_cast<uint2*>(d)              = hip;
    *reinterpret_cast<uint2*>(d + K_DIM)      = mode ? lop : hip;
    *reinterpret_cast<uint2*>(d + 2 * K_DIM)  = mode ? hip : lop;
}

// ---------------------------------------------------------------------------
// GEMM via mma.sync (bf16, fp32 accum):
//   C[m,n] = q14( sum_{k'} A'[m,k'] * B'[n,k'] + bias[n] )
// Tile 128x128, BK=32, 256 threads (8 warps, each 32x64),
// 4-stage cp.async pipeline, ONE __syncthreads per chunk.
// Smem 82.4 KB -> 2 CTAs/SM (forced via __launch_bounds__(256, 2)).
// grid = (12, 64, 2); z selects (x,Wih,gi,bih) vs (h,Whh,gh,bhh).
// ---------------------------------------------------------------------------
#define TILE_M 128
#define TILE_N 128
#define BK 32
#define NCH (KP / BK)          // 48
#define STAGES 4
#define ROWSTRIDE 40           // bf16 elems per smem row (64B data + 16B pad)
#define STAGE_ELEMS (TILE_M * ROWSTRIDE)          // 5120 per operand per stage
#define SM_A_OFF 0
#define SM_B_OFF (STAGES * STAGE_ELEMS)           // 20480
#define SM_BIAS_OFF (2 * STAGES * STAGE_ELEMS)    // 40960 (elems)
#define GSMEM_BYTES (SM_BIAS_OFF * 2 + TILE_N * 4)   // 81920 + 512 = 82432

__device__ __forceinline__ void load_chunk(uint32_t as_base, uint32_t bs_base,
                                           const __nv_bfloat16* __restrict__ Ag,
                                           const __nv_bfloat16* __restrict__ Bg,
                                           int tid)
{
    // per operand: 128 rows x 4 segs(16B) = 512 cp16; 256 threads -> 2 each
    #pragma unroll
    for (int o = 0; o < 2; o++) {
        int lin = tid + o * 256;
        int row = lin >> 2, seg = lin & 3;
        uint32_t off = ((uint32_t)row * ROWSTRIDE + (uint32_t)seg * 8) * 2;
        cp16(as_base + off, Ag + (size_t)row * KP + seg * 8);
        cp16(bs_base + off, Bg + (size_t)row * KP + seg * 8);
    }
}

__global__ __launch_bounds__(256, 2)
void gemm_mma(const float* __restrict__ bias_i, const float* __restrict__ bias_h)
{
    extern __shared__ __align__(16) __nv_bfloat16 sm[];
    float* sb_bias = (float*)(sm + SM_BIAS_OFF);

    const int tid = threadIdx.x;
    const int wid = tid >> 5, lane = tid & 31;
    const int n0 = blockIdx.x * TILE_N;
    const int m0 = blockIdx.y * TILE_M;
    const int z  = blockIdx.z;

    const __nv_bfloat16* __restrict__ A = z ? g_hp  : g_xp;
    const __nv_bfloat16* __restrict__ B = z ? g_whp : g_wip;
    const float* __restrict__ bias = z ? bias_h : bias_i;
    float* __restrict__ C = z ? g_gh : g_gi;

    if (tid < TILE_N) sb_bias[tid] = bias[n0 + tid];

    const uint32_t smb = smem_u32(sm);

    // warp tile: 4x2 grid of warps -> each warp 32 (m) x 64 (n)
    const int wm = (wid & 3) * 32;
    const int wn = (wid >> 2) * 64;
    const int g  = lane >> 2;
    const int tq = lane & 3;

    float d[2][8][4];
    #pragma unroll
    for (int a = 0; a < 2; a++)
        #pragma unroll
        for (int b = 0; b < 8; b++)
            #pragma unroll
            for (int c = 0; c < 4; c++) d[a][b][c] = 0.0f;

    // ldmatrix lane mappings
    const int lm_row = (lane & 15);
    const int lm_hi  = (lane >> 4) & 1;
    const int lb_row = ((lane >> 4) & 1) * 8 + (lane & 7);
    const int lb_seg = (lane >> 3) & 1;

    const __nv_bfloat16* Ag0 = A + (size_t)m0 * KP;
    const __nv_bfloat16* Bg0 = B + (size_t)n0 * KP;

    // Prologue: chunks 0..2 into stages 0..2
    #pragma unroll
    for (int c = 0; c < STAGES - 1; c++) {
        load_chunk(smb + (SM_A_OFF + c * STAGE_ELEMS) * 2,
                   smb + (SM_B_OFF + c * STAGE_ELEMS) * 2,
                   Ag0 + c * BK, Bg0 + c * BK, tid);
        asm volatile("cp.async.commit_group;" ::: "memory");
    }

    for (int c = 0; c < NCH; c++) {
        const int s = c & (STAGES - 1);

        if (c < NCH - 2)       asm volatile("cp.async.wait_group 2;" ::: "memory");
        else if (c == NCH - 2) asm volatile("cp.async.wait_group 1;" ::: "memory");
        else                   asm volatile("cp.async.wait_group 0;" ::: "memory");
        __syncthreads();

        // Prefetch chunk c+3 into stage (c+3)%4 (consumed at iter c-1;
        // the sync above ordered that compute before this write).
        if (c + STAGES - 1 < NCH) {
            const int sp = (c + STAGES - 1) & (STAGES - 1);
            load_chunk(smb + (SM_A_OFF + sp * STAGE_ELEMS) * 2,
                       smb + (SM_B_OFF + sp * STAGE_ELEMS) * 2,
                       Ag0 + (c + STAGES - 1) * BK, Bg0 + (c + STAGES - 1) * BK, tid);
            asm volatile("cp.async.commit_group;" ::: "memory");
        }

        const uint32_t as = smb + (SM_A_OFF + s * STAGE_ELEMS) * 2;
        const uint32_t bs = smb + (SM_B_OFF + s * STAGE_ELEMS) * 2;

        #pragma unroll
        for (int ks = 0; ks < BK / 16; ks++) {
            uint32_t aF[2][4];
            #pragma unroll
            for (int mt = 0; mt < 2; mt++) {
                uint32_t addr = as + (((uint32_t)(wm + mt * 16 + lm_row) * ROWSTRIDE)
                                      + ks * 16 + lm_hi * 8) * 2;
                ldmatrix_x4(aF[mt][0], aF[mt][1], aF[mt][2], aF[mt][3], addr);
            }
            uint32_t bF[8][2];
            #pragma unroll
            for (int nt = 0; nt < 4; nt++) {
                uint32_t r0, r1, r2, r3;
                uint32_t addr = bs + (((uint32_t)(wn + nt * 16 + lb_row) * ROWSTRIDE)
                                      + ks * 16 + lb_seg * 8) * 2;
                ldmatrix_x4(r0, r1, r2, r3, addr);
                bF[nt * 2 + 0][0] = r0; bF[nt * 2 + 0][1] = r1;
                bF[nt * 2 + 1][0] = r2; bF[nt * 2 + 1][1] = r3;
            }
            #pragma unroll
            for (int mt = 0; mt < 2; mt++)
                #pragma unroll
                for (int nt = 0; nt < 8; nt++)
                    mma_bf16(d[mt][nt][0], d[mt][nt][1], d[mt][nt][2], d[mt][nt][3],
                             aF[mt][0], aF[mt][1], aF[mt][2], aF[mt][3],
                             bF[nt][0], bF[nt][1]);
        }
    }

    // Epilogue: +bias, q14, store.
    #pragma unroll
    for (int mt = 0; mt < 2; mt++) {
        int r0 = m0 + wm + mt * 16 + g;
        int r1 = r0 + 8;
        #pragma unroll
        for (int nt = 0; nt < 8; nt++) {
            int cl = wn + nt * 8 + tq * 2;
            float b0 = sb_bias[cl], b1 = sb_bias[cl + 1];
            float2 o0, o1;
            o0.x = qround(d[mt][nt][0] + b0, S14F, I14F);
            o0.y = qround(d[mt][nt][1] + b1, S14F, I14F);
            o1.x = qround(d[mt][nt][2] + b0, S14F, I14F);
            o1.y = qround(d[mt][nt][3] + b1, S14F, I14F);
            *reinterpret_cast<float2*>(C + (size_t)r0 * N_DIM + n0 + cl) = o0;
            *reinterpret_cast<float2*>(C + (size_t)r1 * N_DIM + n0 + cl) = o1;
        }
    }
}

// ---------------------------------------------------------------------------
// Fused gate epilogue over [B, H], float4-vectorized.
// ---------------------------------------------------------------------------
__global__ __launch_bounds__(256)
void qgru_epilogue(const float* __restrict__ hidden, float* __restrict__ out)
{
    int idx = blockIdx.x * blockDim.x + threadIdx.x;
    if (idx >= (M_DIM * H_DIM) / 4) return;
    int b = idx >> 7;
    int h = (idx & 127) << 2;

    const float* gib = g_gi + (size_t)b * N_DIM;
    const float* ghb = g_gh + (size_t)b * N_DIM;

    float4 ir = *reinterpret_cast<const float4*>(gib + h);
    float4 ii = *reinterpret_cast<const float4*>(gib + h + H_DIM);
    float4 in_ = *reinterpret_cast<const float4*>(gib + h + 2 * H_DIM);
    float4 hr = *reinterpret_cast<const float4*>(ghb + h);
    float4 hi = *reinterpret_cast<const float4*>(ghb + h + H_DIM);
    float4 hn = *reinterpret_cast<const float4*>(ghb + h + 2 * H_DIM);
    float4 hd = *reinterpret_cast<const float4*>(hidden + (size_t)b * H_DIM + h);

    float irA[4] = {ir.x, ir.y, ir.z, ir.w};
    float iiA[4] = {ii.x, ii.y, ii.z, ii.w};
    float inA[4] = {in_.x, in_.y, in_.z, in_.w};
    float hrA[4] = {hr.x, hr.y, hr.z, hr.w};
    float hiA[4] = {hi.x, hi.y, hi.z, hi.w};
    float hnA[4] = {hn.x, hn.y, hn.z, hn.w};
    float hdA[4] = {hd.x, hd.y, hd.z, hd.w};
    float res[4];

    #pragma unroll
    for (int l = 0; l < 4; l++) {
        float rg  = qsig(__fadd_rn(irA[l], hrA[l]));
        float ig  = qsig(__fadd_rn(iiA[l], hiA[l]));
        float hnq = qround(hnA[l], Q27F, IQ27F);
        float rh  = qround(__fmul_rn(rg, hnq), S15F, I15F);
        float ng  = qtanhf_(__fadd_rn(rh, inA[l]));
        float nh  = qround(hdA[l], S15F, I15F);
        res[l] = __fadd_rn(ng, __fmul_rn(ig, __fsub_rn(nh, ng)));
    }

    float4 o = {res[0], res[1], res[2], res[3]};
    *reinterpret_cast<float4*>(out + (size_t)b * H_DIM + h) = o;
}

// ---------------------------------------------------------------------------
extern "C" void kernel_launch(void* const* d_in, const int* in_sizes, int n_in,
                              void* d_out, int out_size)
{
    const float* x   = (const float*)d_in[0];
    const float* h   = (const float*)d_in[1];
    const float* wih = (const float*)d_in[2];
    const float* whh = (const float*)d_in[3];
    const float* bih = (const float*)d_in[4];
    const float* bhh = (const float*)d_in[5];
    float* out = (float*)d_out;

    cudaFuncSetAttribute(gemm_mma, cudaFuncAttributeMaxDynamicSharedMemorySize,
                         GSMEM_BYTES);

    __nv_bfloat16 *xp, *hp, *wip, *whp;
    cudaGetSymbolAddress((void**)&xp,  g_xp);
    cudaGetSymbolAddress((void**)&hp,  g_hp);
    cudaGetSymbolAddress((void**)&wip, g_wip);
    cudaGetSymbolAddress((void**)&whp, g_whp);

    const int nA4 = M_DIM * (K_DIM / 4);
    const int nW4 = N_DIM * (K_DIM / 4);
    split_pack<<<(nA4 + 255) / 256, 256>>>(x,   xp,  M_DIM, 0);
    split_pack<<<(nA4 + 255) / 256, 256>>>(h,   hp,  M_DIM, 0);
    split_pack<<<(nW4 + 255) / 256, 256>>>(wih, wip, N_DIM, 1);
    split_pack<<<(nW4 + 255) / 256, 256>>>(whh, whp, N_DIM, 1);

    dim3 grid(N_DIM / TILE_N, M_DIM / TILE_M, 2);   // (12, 64, 2)
    gemm_mma<<<grid, 256, GSMEM_BYTES>>>(bih, bhh);

    int total = (M_DIM * H_DIM) / 4;
    qgru_epilogue<<<(total + 255) / 256, 256>>>(h, out);
}

// round 12
// speedup vs baseline: 1.8143x; 1.0828x over previous
#include <cuda_runtime.h>
#include <cuda_bf16.h>
#include <cstdint>
#include <cstddef>

// Problem dims (fixed by the dataset)
#define M_DIM 8192
#define N_DIM 1536
#define K_DIM 512
#define H_DIM 512
#define KP    (3 * K_DIM)     // packed K' = 1536

// ---------------------------------------------------------------------------
// Device-global scratch (no cudaMalloc allowed)
// ---------------------------------------------------------------------------
__device__ float g_gi[(size_t)M_DIM * N_DIM];
__device__ float g_gh[(size_t)M_DIM * N_DIM];

// Packed split operands: A' = [hi | hi | lo], B' = [hi | lo | hi]
__device__ __nv_bfloat16 g_xp[(size_t)M_DIM * KP];
__device__ __nv_bfloat16 g_hp[(size_t)M_DIM * KP];
__device__ __nv_bfloat16 g_wip[(size_t)N_DIM * KP];
__device__ __nv_bfloat16 g_whp[(size_t)N_DIM * KP];

// ---------------------------------------------------------------------------
// Quantization helpers (exact fp32 semantics, no FMA contraction)
// ---------------------------------------------------------------------------
#define Q27F   134217728.0f
#define IQ27F  7.450580596923828125e-9f    // 2^-27
#define Q31F   2147483648.0f
#define IQ16F  1.52587890625e-5f           // 2^-16
#define S15F   32768.0f
#define I15F   3.0517578125e-5f            // 2^-15
#define S14F   16384.0f
#define I14F   6.103515625e-5f             // 2^-14

__device__ __forceinline__ float qround(float x, float s, float inv) {
    return __fmul_rn(floorf(__fadd_rn(__fmul_rn(x, s), 0.5f)), inv);
}

__device__ __forceinline__ float qsig(float x) {
    float t = floorf(__fadd_rn(__fmul_rn(x, Q27F), 0.5f));
    t = fminf(fmaxf(t, -2147483648.0f), 2147483648.0f);
    float xr = __fmul_rn(t, IQ27F);
    float s  = 1.0f / (1.0f + expf(-xr));
    float q31 = floorf(__fadd_rn(__fmul_rn(s, Q31F), 0.5f));
    float q15 = floorf(__fadd_rn(__fmul_rn(q31, IQ16F), 0.5f));
    return __fmul_rn(q15, I15F);
}

__device__ __forceinline__ float qtanhf_(float x) {
    float t = floorf(__fadd_rn(__fmul_rn(x, Q27F), 0.5f));
    t = fminf(fmaxf(t, -2147483648.0f), 2147483648.0f);
    float xr = __fmul_rn(t, IQ27F);
    float s  = tanhf(xr);
    float q31 = floorf(__fadd_rn(__fmul_rn(s, Q31F), 0.5f));
    float q15 = floorf(__fadd_rn(__fmul_rn(q31, IQ16F), 0.5f));
    return __fmul_rn(q15, I15F);
}

// ---------------------------------------------------------------------------
// PTX helpers (baseline sm_103-safe: mma.sync / ldmatrix / cp.async only)
// ---------------------------------------------------------------------------
__device__ __forceinline__ uint32_t smem_u32(const void* p) {
    uint32_t a;
    asm("{ .reg .u64 t; cvta.to.shared.u64 t, %1; cvt.u32.u64 %0, t; }" : "=r"(a) : "l"(p));
    return a;
}

__device__ __forceinline__ void cp16(uint32_t dst, const void* src) {
    asm volatile("cp.async.cg.shared.global [%0], [%1], 16;" :: "r"(dst), "l"(src) : "memory");
}

__device__ __forceinline__ void ldmatrix_x4(uint32_t& r0, uint32_t& r1,
                                            uint32_t& r2, uint32_t& r3,
                                            uint32_t addr) {
    asm volatile("ldmatrix.sync.aligned.m8n8.x4.shared.b16 {%0,%1,%2,%3}, [%4];"
                 : "=r"(r0), "=r"(r1), "=r"(r2), "=r"(r3) : "r"(addr));
}

__device__ __forceinline__ void mma_bf16(float& d0, float& d1, float& d2, float& d3,
                                         uint32_t a0, uint32_t a1, uint32_t a2, uint32_t a3,
                                         uint32_t b0, uint32_t b1) {
    asm volatile(
        "mma.sync.aligned.m16n8k16.row.col.f32.bf16.bf16.f32 "
        "{%0,%1,%2,%3}, {%4,%5,%6,%7}, {%8,%9}, {%0,%1,%2,%3};"
        : "+f"(d0), "+f"(d1), "+f"(d2), "+f"(d3)
        : "r"(a0), "r"(a1), "r"(a2), "r"(a3), "r"(b0), "r"(b1));
}

// ---------------------------------------------------------------------------
// fp32 -> packed bf16 hi/lo split, float4-vectorized (4 elems / thread).
// mode 0 (activations A'): [hi | hi | lo]
// mode 1 (weights     B'): [hi | lo | hi]
// ---------------------------------------------------------------------------
__global__ __launch_bounds__(256)
void split_pack(const float* __restrict__ src, __nv_bfloat16* __restrict__ dst,
                int rows, int mode)
{
    int i4 = blockIdx.x * blockDim.x + threadIdx.x;
    if (i4 >= rows * (K_DIM / 4)) return;
    int m = i4 >> 7;             // / (K_DIM/4)
    int k = (i4 & 127) << 2;
    float4 v = *reinterpret_cast<const float4*>(src + (size_t)m * K_DIM + k);
    float vv[4] = {v.x, v.y, v.z, v.w};
    __nv_bfloat16 hi[4], lo[4];
    #pragma unroll
    for (int j = 0; j < 4; j++) {
        hi[j] = __float2bfloat16_rn(vv[j]);
        lo[j] = __float2bfloat16_rn(vv[j] - __bfloat162float(hi[j]));
    }
    __nv_bfloat16* d = dst + (size_t)m * KP + k;
    uint2 hip = {((uint32_t)__bfloat16_as_ushort(hi[1]) << 16) | __bfloat16_as_ushort(hi[0]),
                 ((uint32_t)__bfloat16_as_ushort(hi[3]) << 16) | __bfloat16_as_ushort(hi[2])};
    uint2 lop = {((uint32_t)__bfloat16_as_ushort(lo[1]) << 16) | __bfloat16_as_ushort(lo[0]),
                 ((uint32_t)__bfloat16_as_ushort(lo[3]) << 16) | __bfloat16_as_ushort(lo[2])};
    *reinterpret_cast<uint2*>(d)              = hip;
    *reinterpret_cast<uint2*>(d + K_DIM)      = mode ? lop : hip;
    *reinterpret_cast<uint2*>(d + 2 * K_DIM)  = mode ? hip : lop;
}

// ---------------------------------------------------------------------------
// GEMM via mma.sync (bf16, fp32 accum):
//   C[m,n] = q14( sum_{k'} A'[m,k'] * B'[n,k'] + bias[n] )
// Tile 128x128, BK=32, 128 threads (4 warps in 2x2, each warp 64x64),
// 4-stage cp.async pipeline, ONE __syncthreads per chunk.
// Smem 82.4 KB -> 2 CTAs/SM (forced via __launch_bounds__(128, 2)).
// grid = (12, 64, 2); z selects (x,Wih,gi,bih) vs (h,Whh,gh,bhh).
// ---------------------------------------------------------------------------
#define TILE_M 128
#define TILE_N 128
#define BK 32
#define NCH (KP / BK)          // 48
#define STAGES 4
#define ROWSTRIDE 40           // bf16 elems per smem row (64B data + 16B pad)
#define STAGE_ELEMS (TILE_M * ROWSTRIDE)          // 5120 per operand per stage
#define SM_A_OFF 0
#define SM_B_OFF (STAGES * STAGE_ELEMS)           // 20480
#define SM_BIAS_OFF (2 * STAGES * STAGE_ELEMS)    // 40960 (elems)
#define GSMEM_BYTES (SM_BIAS_OFF * 2 + TILE_N * 4)   // 82432

__device__ __forceinline__ void load_chunk(uint32_t as_base, uint32_t bs_base,
                                           const __nv_bfloat16* __restrict__ Ag,
                                           const __nv_bfloat16* __restrict__ Bg,
                                           int tid)
{
    // per operand: 128 rows x 4 segs(16B) = 512 cp16; 128 threads -> 4 each
    #pragma unroll
    for (int o = 0; o < 4; o++) {
        int lin = tid + o * 128;
        int row = lin >> 2, seg = lin & 3;
        uint32_t off = ((uint32_t)row * ROWSTRIDE + (uint32_t)seg * 8) * 2;
        cp16(as_base + off, Ag + (size_t)row * KP + seg * 8);
        cp16(bs_base + off, Bg + (size_t)row * KP + seg * 8);
    }
}

__global__ __launch_bounds__(128, 2)
void gemm_mma(const float* __restrict__ bias_i, const float* __restrict__ bias_h)
{
    extern __shared__ __align__(16) __nv_bfloat16 sm[];
    float* sb_bias = (float*)(sm + SM_BIAS_OFF);

    const int tid = threadIdx.x;
    const int wid = tid >> 5, lane = tid & 31;
    const int n0 = blockIdx.x * TILE_N;
    const int m0 = blockIdx.y * TILE_M;
    const int z  = blockIdx.z;

    const __nv_bfloat16* __restrict__ A = z ? g_hp  : g_xp;
    const __nv_bfloat16* __restrict__ B = z ? g_whp : g_wip;
    const float* __restrict__ bias = z ? bias_h : bias_i;
    float* __restrict__ C = z ? g_gh : g_gi;

    sb_bias[tid] = bias[n0 + tid];

    const uint32_t smb = smem_u32(sm);

    // warp tile: 2x2 grid of warps -> each warp 64 (m) x 64 (n)
    const int wm = (wid & 1) * 64;
    const int wn = (wid >> 1) * 64;
    const int g  = lane >> 2;
    const int tq = lane & 3;

    float d[4][8][4];
    #pragma unroll
    for (int a = 0; a < 4; a++)
        #pragma unroll
        for (int b = 0; b < 8; b++)
            #pragma unroll
            for (int c = 0; c < 4; c++) d[a][b][c] = 0.0f;

    // ldmatrix lane mappings
    const int lm_row = (lane & 15);
    const int lm_hi  = (lane >> 4) & 1;
    const int lb_row = ((lane >> 4) & 1) * 8 + (lane & 7);
    const int lb_seg = (lane >> 3) & 1;

    const __nv_bfloat16* Ag0 = A + (size_t)m0 * KP;
    const __nv_bfloat16* Bg0 = B + (size_t)n0 * KP;

    // Prologue: chunks 0..2 into stages 0..2
    #pragma unroll
    for (int c = 0; c < STAGES - 1; c++) {
        load_chunk(smb + (SM_A_OFF + c * STAGE_ELEMS) * 2,
                   smb + (SM_B_OFF + c * STAGE_ELEMS) * 2,
                   Ag0 + c * BK, Bg0 + c * BK, tid);
        asm volatile("cp.async.commit_group;" ::: "memory");
    }

    for (int c = 0; c < NCH; c++) {
        const int s = c & (STAGES - 1);

        if (c < NCH - 2)       asm volatile("cp.async.wait_group 2;" ::: "memory");
        else if (c == NCH - 2) asm volatile("cp.async.wait_group 1;" ::: "memory");
        else                   asm volatile("cp.async.wait_group 0;" ::: "memory");
        __syncthreads();

        // Prefetch chunk c+3 into stage (c+3)%4 (consumed at iter c-1;
        // the sync above ordered that compute before this write).
        if (c + STAGES - 1 < NCH) {
            const int sp = (c + STAGES - 1) & (STAGES - 1);
            load_chunk(smb + (SM_A_OFF + sp * STAGE_ELEMS) * 2,
                       smb + (SM_B_OFF + sp * STAGE_ELEMS) * 2,
                       Ag0 + (c + STAGES - 1) * BK, Bg0 + (c + STAGES - 1) * BK, tid);
            asm volatile("cp.async.commit_group;" ::: "memory");
        }

        const uint32_t as = smb + (SM_A_OFF + s * STAGE_ELEMS) * 2;
        const uint32_t bs = smb + (SM_B_OFF + s * STAGE_ELEMS) * 2;

        #pragma unroll
        for (int ks = 0; ks < BK / 16; ks++) {
            uint32_t aF[4][4];
            #pragma unroll
            for (int mt = 0; mt < 4; mt++) {
                uint32_t addr = as + (((uint32_t)(wm + mt * 16 + lm_row) * ROWSTRIDE)
                                      + ks * 16 + lm_hi * 8) * 2;
                ldmatrix_x4(aF[mt][0], aF[mt][1], aF[mt][2], aF[mt][3], addr);
            }
            uint32_t bF[8][2];
            #pragma unroll
            for (int nt = 0; nt < 4; nt++) {
                uint32_t r0, r1, r2, r3;
                uint32_t addr = bs + (((uint32_t)(wn + nt * 16 + lb_row) * ROWSTRIDE)
                                      + ks * 16 + lb_seg * 8) * 2;
                ldmatrix_x4(r0, r1, r2, r3, addr);
                bF[nt * 2 + 0][0] = r0; bF[nt * 2 + 0][1] = r1;
                bF[nt * 2 + 1][0] = r2; bF[nt * 2 + 1][1] = r3;
            }
            #pragma unroll
            for (int mt = 0; mt < 4; mt++)
                #pragma unroll
                for (int nt = 0; nt < 8; nt++)
                    mma_bf16(d[mt][nt][0], d[mt][nt][1], d[mt][nt][2], d[mt][nt][3],
                             aF[mt][0], aF[mt][1], aF[mt][2], aF[mt][3],
                             bF[nt][0], bF[nt][1]);
        }
    }

    // Epilogue: +bias, q14, store.
    #pragma unroll
    for (int mt = 0; mt < 4; mt++) {
        int r0 = m0 + wm + mt * 16 + g;
        int r1 = r0 + 8;
        #pragma unroll
        for (int nt = 0; nt < 8; nt++) {
            int cl = wn + nt * 8 + tq * 2;
            float b0 = sb_bias[cl], b1 = sb_bias[cl + 1];
            float2 o0, o1;
            o0.x = qround(d[mt][nt][0] + b0, S14F, I14F);
            o0.y = qround(d[mt][nt][1] + b1, S14F, I14F);
            o1.x = qround(d[mt][nt][2] + b0, S14F, I14F);
            o1.y = qround(d[mt][nt][3] + b1, S14F, I14F);
            *reinterpret_cast<float2*>(C + (size_t)r0 * N_DIM + n0 + cl) = o0;
            *reinterpret_cast<float2*>(C + (size_t)r1 * N_DIM + n0 + cl) = o1;
        }
    }
}

// ---------------------------------------------------------------------------
// Fused gate epilogue over [B, H], float4-vectorized.
// ---------------------------------------------------------------------------
__global__ __launch_bounds__(256)
void qgru_epilogue(const float* __restrict__ hidden, float* __restrict__ out)
{
    int idx = blockIdx.x * blockDim.x + threadIdx.x;
    if (idx >= (M_DIM * H_DIM) / 4) return;
    int b = idx >> 7;
    int h = (idx & 127) << 2;

    const float* gib = g_gi + (size_t)b * N_DIM;
    const float* ghb = g_gh + (size_t)b * N_DIM;

    float4 ir = *reinterpret_cast<const float4*>(gib + h);
    float4 ii = *reinterpret_cast<const float4*>(gib + h + H_DIM);
    float4 in_ = *reinterpret_cast<const float4*>(gib + h + 2 * H_DIM);
    float4 hr = *reinterpret_cast<const float4*>(ghb + h);
    float4 hi = *reinterpret_cast<const float4*>(ghb + h + H_DIM);
    float4 hn = *reinterpret_cast<const float4*>(ghb + h + 2 * H_DIM);
    float4 hd = *reinterpret_cast<const float4*>(hidden + (size_t)b * H_DIM + h);

    float irA[4] = {ir.x, ir.y, ir.z, ir.w};
    float iiA[4] = {ii.x, ii.y, ii.z, ii.w};
    float inA[4] = {in_.x, in_.y, in_.z, in_.w};
    float hrA[4] = {hr.x, hr.y, hr.z, hr.w};
    float hiA[4] = {hi.x, hi.y, hi.z, hi.w};
    float hnA[4] = {hn.x, hn.y, hn.z, hn.w};
    float hdA[4] = {hd.x, hd.y, hd.z, hd.w};
    float res[4];

    #pragma unroll
    for (int l = 0; l < 4; l++) {
        float rg  = qsig(__fadd_rn(irA[l], hrA[l]));
        float ig  = qsig(__fadd_rn(iiA[l], hiA[l]));
        float hnq = qround(hnA[l], Q27F, IQ27F);
        float rh  = qround(__fmul_rn(rg, hnq), S15F, I15F);
        float ng  = qtanhf_(__fadd_rn(rh, inA[l]));
        float nh  = qround(hdA[l], S15F, I15F);
        res[l] = __fadd_rn(ng, __fmul_rn(ig, __fsub_rn(nh, ng)));
    }

    float4 o = {res[0], res[1], res[2], res[3]};
    *reinterpret_cast<float4*>(out + (size_t)b * H_DIM + h) = o;
}

// ---------------------------------------------------------------------------
extern "C" void kernel_launch(void* const* d_in, const int* in_sizes, int n_in,
                              void* d_out, int out_size)
{
    const float* x   = (const float*)d_in[0];
    const float* h   = (const float*)d_in[1];
    const float* wih = (const float*)d_in[2];
    const float* whh = (const float*)d_in[3];
    const float* bih = (const float*)d_in[4];
    const float* bhh = (const float*)d_in[5];
    float* out = (float*)d_out;

    cudaFuncSetAttribute(gemm_mma, cudaFuncAttributeMaxDynamicSharedMemorySize,
                         GSMEM_BYTES);

    __nv_bfloat16 *xp, *hp, *wip, *whp;
    cudaGetSymbolAddress((void**)&xp,  g_xp);
    cudaGetSymbolAddress((void**)&hp,  g_hp);
    cudaGetSymbolAddress((void**)&wip, g_wip);
    cudaGetSymbolAddress((void**)&whp, g_whp);

    const int nA4 = M_DIM * (K_DIM / 4);
    const int nW4 = N_DIM * (K_DIM / 4);
    split_pack<<<(nA4 + 255) / 256, 256>>>(x,   xp,  M_DIM, 0);
    split_pack<<<(nA4 + 255) / 256, 256>>>(h,   hp,  M_DIM, 0);
    split_pack<<<(nW4 + 255) / 256, 256>>>(wih, wip, N_DIM, 1);
    split_pack<<<(nW4 + 255) / 256, 256>>>(whh, whp, N_DIM, 1);

    dim3 grid(N_DIM / TILE_N, M_DIM / TILE_M, 2);   // (12, 64, 2)
    gemm_mma<<<grid, 128, GSMEM_BYTES>>>(bih, bhh);

    int total = (M_DIM * H_DIM) / 4;
    qgru_epilogue<<<(total + 255) / 256, 256>>>(h, out);
}

// round 13
// speedup vs baseline: 1.8704x; 1.0309x over previous
#include <cuda_runtime.h>
#include <cuda_bf16.h>
#include <cstdint>
#include <cstddef>

// Problem dims (fixed by the dataset)
#define M_DIM 8192
#define N_DIM 1536
#define K_DIM 512
#define H_DIM 512
#define KP    (3 * K_DIM)     // packed K' = 1536

// ---------------------------------------------------------------------------
// Device-global scratch (no cudaMalloc allowed)
// ---------------------------------------------------------------------------
__device__ float g_gi[(size_t)M_DIM * N_DIM];
__device__ float g_gh[(size_t)M_DIM * N_DIM];

// Packed split operands: A' = [hi | hi | lo], B' = [hi | lo | hi]
__device__ __nv_bfloat16 g_xp[(size_t)M_DIM * KP];
__device__ __nv_bfloat16 g_hp[(size_t)M_DIM * KP];
__device__ __nv_bfloat16 g_wip[(size_t)N_DIM * KP];
__device__ __nv_bfloat16 g_whp[(size_t)N_DIM * KP];

// ---------------------------------------------------------------------------
// Quantization helpers (exact fp32 semantics, no FMA contraction)
// ---------------------------------------------------------------------------
#define Q27F   134217728.0f
#define IQ27F  7.450580596923828125e-9f    // 2^-27
#define Q31F   2147483648.0f
#define IQ16F  1.52587890625e-5f           // 2^-16
#define S15F   32768.0f
#define I15F   3.0517578125e-5f            // 2^-15
#define S14F   16384.0f
#define I14F   6.103515625e-5f             // 2^-14

__device__ __forceinline__ float qround(float x, float s, float inv) {
    return __fmul_rn(floorf(__fadd_rn(__fmul_rn(x, s), 0.5f)), inv);
}

__device__ __forceinline__ float qsig(float x) {
    float t = floorf(__fadd_rn(__fmul_rn(x, Q27F), 0.5f));
    t = fminf(fmaxf(t, -2147483648.0f), 2147483648.0f);
    float xr = __fmul_rn(t, IQ27F);
    float s  = 1.0f / (1.0f + expf(-xr));
    float q31 = floorf(__fadd_rn(__fmul_rn(s, Q31F), 0.5f));
    float q15 = floorf(__fadd_rn(__fmul_rn(q31, IQ16F), 0.5f));
    return __fmul_rn(q15, I15F);
}

__device__ __forceinline__ float qtanhf_(float x) {
    float t = floorf(__fadd_rn(__fmul_rn(x, Q27F), 0.5f));
    t = fminf(fmaxf(t, -2147483648.0f), 2147483648.0f);
    float xr = __fmul_rn(t, IQ27F);
    float s  = tanhf(xr);
    float q31 = floorf(__fadd_rn(__fmul_rn(s, Q31F), 0.5f));
    float q15 = floorf(__fadd_rn(__fmul_rn(q31, IQ16F), 0.5f));
    return __fmul_rn(q15, I15F);
}

// ---------------------------------------------------------------------------
// PTX helpers (baseline sm_103-safe: mma.sync / ldmatrix / cp.async only)
// ---------------------------------------------------------------------------
__device__ __forceinline__ uint32_t smem_u32(const void* p) {
    uint32_t a;
    asm("{ .reg .u64 t; cvta.to.shared.u64 t, %1; cvt.u32.u64 %0, t; }" : "=r"(a) : "l"(p));
    return a;
}

__device__ __forceinline__ void cp16(uint32_t dst, const void* src) {
    asm volatile("cp.async.cg.shared.global [%0], [%1], 16;" :: "r"(dst), "l"(src) : "memory");
}

__device__ __forceinline__ void ldmatrix_x4(uint32_t& r0, uint32_t& r1,
                                            uint32_t& r2, uint32_t& r3,
                                            uint32_t addr) {
    asm volatile("ldmatrix.sync.aligned.m8n8.x4.shared.b16 {%0,%1,%2,%3}, [%4];"
                 : "=r"(r0), "=r"(r1), "=r"(r2), "=r"(r3) : "r"(addr));
}

__device__ __forceinline__ void mma_bf16(float& d0, float& d1, float& d2, float& d3,
                                         uint32_t a0, uint32_t a1, uint32_t a2, uint32_t a3,
                                         uint32_t b0, uint32_t b1) {
    asm volatile(
        "mma.sync.aligned.m16n8k16.row.col.f32.bf16.bf16.f32 "
        "{%0,%1,%2,%3}, {%4,%5,%6,%7}, {%8,%9}, {%0,%1,%2,%3};"
        : "+f"(d0), "+f"(d1), "+f"(d2), "+f"(d3)
        : "r"(a0), "r"(a1), "r"(a2), "r"(a3), "r"(b0), "r"(b1));
}

// ---------------------------------------------------------------------------
// Merged fp32 -> packed bf16 hi/lo split for ALL FOUR tensors in one launch.
// Linear i4-index ranges: [0, NA4) -> x, [NA4, 2*NA4) -> h,
// [2*NA4, 2*NA4+NW4) -> wih, [.., +NW4) -> whh.
// mode 0 (activations A'): [hi | hi | lo];  mode 1 (weights B'): [hi | lo | hi]
// ---------------------------------------------------------------------------
#define NA4 (M_DIM * (K_DIM / 4))     // 262144
#define NW4 (N_DIM * (K_DIM / 4))     // 49152
#define NSPLIT4 (2 * NA4 + 2 * NW4)   // 622592

__global__ __launch_bounds__(256)
void split_pack_all(const float* __restrict__ x, const float* __restrict__ h,
                    const float* __restrict__ wih, const float* __restrict__ whh)
{
    int gi4 = blockIdx.x * blockDim.x + threadIdx.x;
    if (gi4 >= NSPLIT4) return;

    const float* src;
    __nv_bfloat16* dst;
    int i4, mode;
    if (gi4 < NA4)                  { src = x;   dst = g_xp;  i4 = gi4;               mode = 0; }
    else if (gi4 < 2 * NA4)         { src = h;   dst = g_hp;  i4 = gi4 - NA4;         mode = 0; }
    else if (gi4 < 2 * NA4 + NW4)   { src = wih; dst = g_wip; i4 = gi4 - 2 * NA4;     mode = 1; }
    else                            { src = whh; dst = g_whp; i4 = gi4 - 2 * NA4 - NW4; mode = 1; }

    int m = i4 >> 7;             // / (K_DIM/4)
    int k = (i4 & 127) << 2;
    float4 v = *reinterpret_cast<const float4*>(src + (size_t)m * K_DIM + k);
    float vv[4] = {v.x, v.y, v.z, v.w};
    __nv_bfloat16 hi[4], lo[4];
    #pragma unroll
    for (int j = 0; j < 4; j++) {
        hi[j] = __float2bfloat16_rn(vv[j]);
        lo[j] = __float2bfloat16_rn(vv[j] - __bfloat162float(hi[j]));
    }
    __nv_bfloat16* d = dst + (size_t)m * KP + k;
    uint2 hip = {((uint32_t)__bfloat16_as_ushort(hi[1]) << 16) | __bfloat16_as_ushort(hi[0]),
                 ((uint32_t)__bfloat16_as_ushort(hi[3]) << 16) | __bfloat16_as_ushort(hi[2])};
    uint2 lop = {((uint32_t)__bfloat16_as_ushort(lo[1]) << 16) | __bfloat16_as_ushort(lo[0]),
                 ((uint32_t)__bfloat16_as_ushort(lo[3]) << 16) | __bfloat16_as_ushort(lo[2])};
    *reinterpret_cast<uint2*>(d)              = hip;
    *reinterpret_cast<uint2*>(d + K_DIM)      = mode ? lop : hip;
    *reinterpret_cast<uint2*>(d + 2 * K_DIM)  = mode ? hip : lop;
}

// ---------------------------------------------------------------------------
// GEMM via mma.sync (bf16, fp32 accum):
//   C[m,n] = q14( sum_{k'} A'[m,k'] * B'[n,k'] + bias[n] )
// Tile 128x128, BK=64, 128 threads (4 warps in 2x2, each warp 64x64),
// 3-stage cp.async pipeline, ONE __syncthreads per chunk.
// Smem 111.1 KB -> 2 CTAs/SM (222 KB of 228 KB).
// grid = (12, 64, 2); z selects (x,Wih,gi,bih) vs (h,Whh,gh,bhh).
// ---------------------------------------------------------------------------
#define TILE_M 128
#define TILE_N 128
#define BK 64
#define NCH (KP / BK)          // 24
#define STAGES 3
#define ROWSTRIDE 72           // bf16 elems per smem row (128B data + 16B pad)
#define STAGE_ELEMS (TILE_M * ROWSTRIDE)          // 9216 per operand per stage
#define SM_A_OFF 0
#define SM_B_OFF (STAGES * STAGE_ELEMS)           // 27648
#define SM_BIAS_OFF (2 * STAGES * STAGE_ELEMS)    // 55296 (elems)
#define GSMEM_BYTES (SM_BIAS_OFF * 2 + TILE_N * 4)   // 110592 + 512 = 111104

__device__ __forceinline__ void load_chunk(uint32_t as_base, uint32_t bs_base,
                                           const __nv_bfloat16* __restrict__ Ag,
                                           const __nv_bfloat16* __restrict__ Bg,
                                           int tid)
{
    // per operand: 128 rows x 8 segs(16B) = 1024 cp16; 128 threads -> 8 each
    #pragma unroll
    for (int o = 0; o < 8; o++) {
        int lin = tid + o * 128;
        int row = lin >> 3, seg = lin & 7;
        uint32_t off = ((uint32_t)row * ROWSTRIDE + (uint32_t)seg * 8) * 2;
        cp16(as_base + off, Ag + (size_t)row * KP + seg * 8);
        cp16(bs_base + off, Bg + (size_t)row * KP + seg * 8);
    }
}

__global__ __launch_bounds__(128, 2)
void gemm_mma(const float* __restrict__ bias_i, const float* __restrict__ bias_h)
{
    extern __shared__ __align__(16) __nv_bfloat16 sm[];
    float* sb_bias = (float*)(sm + SM_BIAS_OFF);

    const int tid = threadIdx.x;
    const int wid = tid >> 5, lane = tid & 31;
    const int n0 = blockIdx.x * TILE_N;
    const int m0 = blockIdx.y * TILE_M;
    const int z  = blockIdx.z;

    const __nv_bfloat16* __restrict__ A = z ? g_hp  : g_xp;
    const __nv_bfloat16* __restrict__ B = z ? g_whp : g_wip;
    const float* __restrict__ bias = z ? bias_h : bias_i;
    float* __restrict__ C = z ? g_gh : g_gi;

    sb_bias[tid] = bias[n0 + tid];

    const uint32_t smb = smem_u32(sm);

    // warp tile: 2x2 grid of warps -> each warp 64 (m) x 64 (n)
    const int wm = (wid & 1) * 64;
    const int wn = (wid >> 1) * 64;
    const int g  = lane >> 2;
    const int tq = lane & 3;

    float d[4][8][4];
    #pragma unroll
    for (int a = 0; a < 4; a++)
        #pragma unroll
        for (int b = 0; b < 8; b++)
            #pragma unroll
            for (int c = 0; c < 4; c++) d[a][b][c] = 0.0f;

    // ldmatrix lane mappings
    const int lm_row = (lane & 15);
    const int lm_hi  = (lane >> 4) & 1;
    const int lb_row = ((lane >> 4) & 1) * 8 + (lane & 7);
    const int lb_seg = (lane >> 3) & 1;

    const __nv_bfloat16* Ag0 = A + (size_t)m0 * KP;
    const __nv_bfloat16* Bg0 = B + (size_t)n0 * KP;

    // Prologue: chunks 0..1 into stages 0..1
    #pragma unroll
    for (int c = 0; c < STAGES - 1; c++) {
        load_chunk(smb + (SM_A_OFF + c * STAGE_ELEMS) * 2,
                   smb + (SM_B_OFF + c * STAGE_ELEMS) * 2,
                   Ag0 + c * BK, Bg0 + c * BK, tid);
        asm volatile("cp.async.commit_group;" ::: "memory");
    }

    int s = 0;
    for (int c = 0; c < NCH; c++) {
        if (c < NCH - 1) asm volatile("cp.async.wait_group 1;" ::: "memory");
        else             asm volatile("cp.async.wait_group 0;" ::: "memory");
        __syncthreads();

        // Prefetch chunk c+2 into stage (c+2)%3 (consumed at iter c-1;
        // the sync above ordered that compute before this write).
        if (c + STAGES - 1 < NCH) {
            int sp = s + (STAGES - 1); if (sp >= STAGES) sp -= STAGES;
            load_chunk(smb + (SM_A_OFF + sp * STAGE_ELEMS) * 2,
                       smb + (SM_B_OFF + sp * STAGE_ELEMS) * 2,
                       Ag0 + (c + STAGES - 1) * BK, Bg0 + (c + STAGES - 1) * BK, tid);
            asm volatile("cp.async.commit_group;" ::: "memory");
        }

        const uint32_t as = smb + (SM_A_OFF + s * STAGE_ELEMS) * 2;
        const uint32_t bs = smb + (SM_B_OFF + s * STAGE_ELEMS) * 2;

        #pragma unroll
        for (int ks = 0; ks < BK / 16; ks++) {
            uint32_t aF[4][4];
            #pragma unroll
            for (int mt = 0; mt < 4; mt++) {
                uint32_t addr = as + (((uint32_t)(wm + mt * 16 + lm_row) * ROWSTRIDE)
                                      + ks * 16 + lm_hi * 8) * 2;
                ldmatrix_x4(aF[mt][0], aF[mt][1], aF[mt][2], aF[mt][3], addr);
            }
            uint32_t bF[8][2];
            #pragma unroll
            for (int nt = 0; nt < 4; nt++) {
                uint32_t r0, r1, r2, r3;
                uint32_t addr = bs + (((uint32_t)(wn + nt * 16 + lb_row) * ROWSTRIDE)
                                      + ks * 16 + lb_seg * 8) * 2;
                ldmatrix_x4(r0, r1, r2, r3, addr);
                bF[nt * 2 + 0][0] = r0; bF[nt * 2 + 0][1] = r1;
                bF[nt * 2 + 1][0] = r2; bF[nt * 2 + 1][1] = r3;
            }
            #pragma unroll
            for (int mt = 0; mt < 4; mt++)
                #pragma unroll
                for (int nt = 0; nt < 8; nt++)
                    mma_bf16(d[mt][nt][0], d[mt][nt][1], d[mt][nt][2], d[mt][nt][3],
                             aF[mt][0], aF[mt][1], aF[mt][2], aF[mt][3],
                             bF[nt][0], bF[nt][1]);
        }
        if (++s >= STAGES) s = 0;
    }

    // Epilogue: +bias, q14, store.
    #pragma unroll
    for (int mt = 0; mt < 4; mt++) {
        int r0 = m0 + wm + mt * 16 + g;
        int r1 = r0 + 8;
        #pragma unroll
        for (int nt = 0; nt < 8; nt++) {
            int cl = wn + nt * 8 + tq * 2;
            float b0 = sb_bias[cl], b1 = sb_bias[cl + 1];
            float2 o0, o1;
            o0.x = qround(d[mt][nt][0] + b0, S14F, I14F);
            o0.y = qround(d[mt][nt][1] + b1, S14F, I14F);
            o1.x = qround(d[mt][nt][2] + b0, S14F, I14F);
            o1.y = qround(d[mt][nt][3] + b1, S14F, I14F);
            *reinterpret_cast<float2*>(C + (size_t)r0 * N_DIM + n0 + cl) = o0;
            *reinterpret_cast<float2*>(C + (size_t)r1 * N_DIM + n0 + cl) = o1;
        }
    }
}

// ---------------------------------------------------------------------------
// Fused gate epilogue over [B, H], float4-vectorized.
// ---------------------------------------------------------------------------
__global__ __launch_bounds__(256)
void qgru_epilogue(const float* __restrict__ hidden, float* __restrict__ out)
{
    int idx = blockIdx.x * blockDim.x + threadIdx.x;
    if (idx >= (M_DIM * H_DIM) / 4) return;
    int b = idx >> 7;
    int h = (idx & 127) << 2;

    const float* gib = g_gi + (size_t)b * N_DIM;
    const float* ghb = g_gh + (size_t)b * N_DIM;

    float4 ir = *reinterpret_cast<const float4*>(gib + h);
    float4 ii = *reinterpret_cast<const float4*>(gib + h + H_DIM);
    float4 in_ = *reinterpret_cast<const float4*>(gib + h + 2 * H_DIM);
    float4 hr = *reinterpret_cast<const float4*>(ghb + h);
    float4 hi = *reinterpret_cast<const float4*>(ghb + h + H_DIM);
    float4 hn = *reinterpret_cast<const float4*>(ghb + h + 2 * H_DIM);
    float4 hd = *reinterpret_cast<const float4*>(hidden + (size_t)b * H_DIM + h);

    float irA[4] = {ir.x, ir.y, ir.z, ir.w};
    float iiA[4] = {ii.x, ii.y, ii.z, ii.w};
    float inA[4] = {in_.x, in_.y, in_.z, in_.w};
    float hrA[4] = {hr.x, hr.y, hr.z, hr.w};
    float hiA[4] = {hi.x, hi.y, hi.z, hi.w};
    float hnA[4] = {hn.x, hn.y, hn.z, hn.w};
    float hdA[4] = {hd.x, hd.y, hd.z, hd.w};
    float res[4];

    #pragma unroll
    for (int l = 0; l < 4; l++) {
        float rg  = qsig(__fadd_rn(irA[l], hrA[l]));
        float ig  = qsig(__fadd_rn(iiA[l], hiA[l]));
        float hnq = qround(hnA[l], Q27F, IQ27F);
        float rh  = qround(__fmul_rn(rg, hnq), S15F, I15F);
        float ng  = qtanhf_(__fadd_rn(rh, inA[l]));
        float nh  = qround(hdA[l], S15F, I15F);
        res[l] = __fadd_rn(ng, __fmul_rn(ig, __fsub_rn(nh, ng)));
    }

    float4 o = {res[0], res[1], res[2], res[3]};
    *reinterpret_cast<float4*>(out + (size_t)b * H_DIM + h) = o;
}

// ---------------------------------------------------------------------------
extern "C" void kernel_launch(void* const* d_in, const int* in_sizes, int n_in,
                              void* d_out, int out_size)
{
    const float* x   = (const float*)d_in[0];
    const float* h   = (const float*)d_in[1];
    const float* wih = (const float*)d_in[2];
    const float* whh = (const float*)d_in[3];
    const float* bih = (const float*)d_in[4];
    const float* bhh = (const float*)d_in[5];
    float* out = (float*)d_out;

    cudaFuncSetAttribute(gemm_mma, cudaFuncAttributeMaxDynamicSharedMemorySize,
                         GSMEM_BYTES);

    split_pack_all<<<(NSPLIT4 + 255) / 256, 256>>>(x, h, wih, whh);

    dim3 grid(N_DIM / TILE_N, M_DIM / TILE_M, 2);   // (12, 64, 2)
    gemm_mma<<<grid, 128, GSMEM_BYTES>>>(bih, bhh);

    int total = (M_DIM * H_DIM) / 4;
    qgru_epilogue<<<(total + 255) / 256, 256>>>(h, out);
}

// round 16
// speedup vs baseline: 2.5756x; 1.3771x over previous
#include <cuda_runtime.h>
#include <cuda_fp16.h>
#include <cstdint>
#include <cstddef>

// Problem dims (fixed by the dataset)
#define M_DIM 8192
#define N_DIM 1536
#define K_DIM 512
#define H_DIM 512
#define KP    (2 * K_DIM)     // packed K' = 1024 (fp16 two-term split)

// ---------------------------------------------------------------------------
// Device-global scratch (no cudaMalloc allowed)
// ---------------------------------------------------------------------------
__device__ float g_gi[(size_t)M_DIM * N_DIM];
__device__ float g_gh[(size_t)M_DIM * N_DIM];

// Packed split operands (fp16): A' = [hi | lo], B' = [hi | hi]
__device__ __half g_xp[(size_t)M_DIM * KP];
__device__ __half g_hp[(size_t)M_DIM * KP];
__device__ __half g_wip[(size_t)N_DIM * KP];
__device__ __half g_whp[(size_t)N_DIM * KP];

// ---------------------------------------------------------------------------
// Quantization helpers (exact fp32 semantics, no FMA contraction)
// ---------------------------------------------------------------------------
#define Q27F   134217728.0f
#define IQ27F  7.450580596923828125e-9f    // 2^-27
#define Q31F   2147483648.0f
#define IQ16F  1.52587890625e-5f           // 2^-16
#define S15F   32768.0f
#define I15F   3.0517578125e-5f            // 2^-15
#define S14F   16384.0f
#define I14F   6.103515625e-5f             // 2^-14

__device__ __forceinline__ float qround(float x, float s, float inv) {
    return __fmul_rn(floorf(__fadd_rn(__fmul_rn(x, s), 0.5f)), inv);
}

__device__ __forceinline__ float qsig(float x) {
    float t = floorf(__fadd_rn(__fmul_rn(x, Q27F), 0.5f));
    t = fminf(fmaxf(t, -2147483648.0f), 2147483648.0f);
    float xr = __fmul_rn(t, IQ27F);
    float s  = 1.0f / (1.0f + expf(-xr));
    float q31 = floorf(__fadd_rn(__fmul_rn(s, Q31F), 0.5f));
    float q15 = floorf(__fadd_rn(__fmul_rn(q31, IQ16F), 0.5f));
    return __fmul_rn(q15, I15F);
}

__device__ __forceinline__ float qtanhf_(float x) {
    float t = floorf(__fadd_rn(__fmul_rn(x, Q27F), 0.5f));
    t = fminf(fmaxf(t, -2147483648.0f), 2147483648.0f);
    float xr = __fmul_rn(t, IQ27F);
    float s  = tanhf(xr);
    float q31 = floorf(__fadd_rn(__fmul_rn(s, Q31F), 0.5f));
    float q15 = floorf(__fadd_rn(__fmul_rn(q31, IQ16F), 0.5f));
    return __fmul_rn(q15, I15F);
}

// ---------------------------------------------------------------------------
// PTX helpers (baseline sm_103-safe: mma.sync / ldmatrix / cp.async only)
// ---------------------------------------------------------------------------
__device__ __forceinline__ uint32_t smem_u32(const void* p) {
    uint32_t a;
    asm("{ .reg .u64 t; cvta.to.shared.u64 t, %1; cvt.u32.u64 %0, t; }" : "=r"(a) : "l"(p));
    return a;
}

__device__ __forceinline__ void cp16(uint32_t dst, const void* src) {
    asm volatile("cp.async.cg.shared.global [%0], [%1], 16;" :: "r"(dst), "l"(src) : "memory");
}

__device__ __forceinline__ void ldmatrix_x4(uint32_t& r0, uint32_t& r1,
                                            uint32_t& r2, uint32_t& r3,
                                            uint32_t addr) {
    asm volatile("ldmatrix.sync.aligned.m8n8.x4.shared.b16 {%0,%1,%2,%3}, [%4];"
                 : "=r"(r0), "=r"(r1), "=r"(r2), "=r"(r3) : "r"(addr));
}

__device__ __forceinline__ void mma_f16(float& d0, float& d1, float& d2, float& d3,
                                        uint32_t a0, uint32_t a1, uint32_t a2, uint32_t a3,
                                        uint32_t b0, uint32_t b1) {
    asm volatile(
        "mma.sync.aligned.m16n8k16.row.col.f32.f16.f16.f32 "
        "{%0,%1,%2,%3}, {%4,%5,%6,%7}, {%8,%9}, {%0,%1,%2,%3};"
        : "+f"(d0), "+f"(d1), "+f"(d2), "+f"(d3)
        : "r"(a0), "r"(a1), "r"(a2), "r"(a3), "r"(b0), "r"(b1));
}

// ---------------------------------------------------------------------------
// Merged fp32 -> packed fp16 hi/lo split for ALL FOUR tensors in one launch.
// mode 0 (activations A'): [hi | lo];  mode 1 (weights B'): [hi | hi]
// ---------------------------------------------------------------------------
#define NA4 (M_DIM * (K_DIM / 4))     // 262144
#define NW4 (N_DIM * (K_DIM / 4))     // 49152
#define NSPLIT4 (2 * NA4 + 2 * NW4)   // 622592

__global__ __launch_bounds__(256)
void split_pack_all(const float* __restrict__ x, const float* __restrict__ h,
                    const float* __restrict__ wih, const float* __restrict__ whh)
{
    int gi4 = blockIdx.x * blockDim.x + threadIdx.x;
    if (gi4 >= NSPLIT4) return;

    const float* src;
    __half* dst;
    int i4, mode;
    if (gi4 < NA4)                  { src = x;   dst = g_xp;  i4 = gi4;                 mode = 0; }
    else if (gi4 < 2 * NA4)         { src = h;   dst = g_hp;  i4 = gi4 - NA4;           mode = 0; }
    else if (gi4 < 2 * NA4 + NW4)   { src = wih; dst = g_wip; i4 = gi4 - 2 * NA4;       mode = 1; }
    else                            { src = whh; dst = g_whp; i4 = gi4 - 2 * NA4 - NW4; mode = 1; }

    int m = i4 >> 7;             // / (K_DIM/4)
    int k = (i4 & 127) << 2;
    float4 v = *reinterpret_cast<const float4*>(src + (size_t)m * K_DIM + k);
    float vv[4] = {v.x, v.y, v.z, v.w};
    __half hi[4], lo[4];
    #pragma unroll
    for (int j = 0; j < 4; j++) {
        hi[j] = __float2half_rn(vv[j]);
        lo[j] = __float2half_rn(vv[j] - __half2float(hi[j]));
    }
    __half* d = dst + (size_t)m * KP + k;
    uint2 hip = {((uint32_t)__half_as_ushort(hi[1]) << 16) | __half_as_ushort(hi[0]),
                 ((uint32_t)__half_as_ushort(hi[3]) << 16) | __half_as_ushort(hi[2])};
    uint2 lop = {((uint32_t)__half_as_ushort(lo[1]) << 16) | __half_as_ushort(lo[0]),
                 ((uint32_t)__half_as_ushort(lo[3]) << 16) | __half_as_ushort(lo[2])};
    *reinterpret_cast<uint2*>(d)          = hip;
    *reinterpret_cast<uint2*>(d + K_DIM)  = mode ? hip : lop;
}

// ---------------------------------------------------------------------------
// GEMM via mma.sync (fp16, fp32 accum):
//   C[m,n] = q14( sum_{k'} A'[m,k'] * B'[n,k'] + bias[n] )
// Tile 128x128, BK=64, 128 threads (4 warps in 2x2, each warp 64x64),
// 3-stage cp.async pipeline, ONE __syncthreads per chunk.
// Smem 111.1 KB -> 2 CTAs/SM.
// grid = (12, 64, 2); z selects (x,Wih,gi,bih) vs (h,Whh,gh,bhh).
// ---------------------------------------------------------------------------
#define TILE_M 128
#define TILE_N 128
#define BK 64
#define NCH (KP / BK)          // 16
#define STAGES 3
#define ROWSTRIDE 72           // fp16 elems per smem row (128B data + 16B pad)
#define STAGE_ELEMS (TILE_M * ROWSTRIDE)          // 9216 per operand per stage
#define SM_A_OFF 0
#define SM_B_OFF (STAGES * STAGE_ELEMS)           // 27648
#define SM_BIAS_OFF (2 * STAGES * STAGE_ELEMS)    // 55296 (elems)
#define GSMEM_BYTES (SM_BIAS_OFF * 2 + TILE_N * 4)   // 111104

__device__ __forceinline__ void load_chunk(uint32_t as_base, uint32_t bs_base,
                                           const __half* __restrict__ Ag,
                                           const __half* __restrict__ Bg,
                                           int tid)
{
    // per operand: 128 rows x 8 segs(16B) = 1024 cp16; 128 threads -> 8 each
    #pragma unroll
    for (int o = 0; o < 8; o++) {
        int lin = tid + o * 128;
        int row = lin >> 3, seg = lin & 7;
        uint32_t off = ((uint32_t)row * ROWSTRIDE + (uint32_t)seg * 8) * 2;
        cp16(as_base + off, Ag + (size_t)row * KP + seg * 8);
        cp16(bs_base + off, Bg + (size_t)row * KP + seg * 8);
    }
}

__global__ __launch_bounds__(128, 2)
void gemm_mma(const float* __restrict__ bias_i, const float* __restrict__ bias_h)
{
    extern __shared__ __align__(16) __half sm[];
    float* sb_bias = (float*)(sm + SM_BIAS_OFF);

    const int tid = threadIdx.x;
    const int wid = tid >> 5, lane = tid & 31;
    const int n0 = blockIdx.x * TILE_N;
    const int m0 = blockIdx.y * TILE_M;
    const int z  = blockIdx.z;

    const __half* __restrict__ A = z ? g_hp  : g_xp;
    const __half* __restrict__ B = z ? g_whp : g_wip;
    const float* __restrict__ bias = z ? bias_h : bias_i;
    float* __restrict__ C = z ? g_gh : g_gi;

    sb_bias[tid] = bias[n0 + tid];

    const uint32_t smb = smem_u32(sm);

    // warp tile: 2x2 grid of warps -> each warp 64 (m) x 64 (n)
    const int wm = (wid & 1) * 64;
    const int wn = (wid >> 1) * 64;
    const int g  = lane >> 2;
    const int tq = lane & 3;

    float d[4][8][4];
    #pragma unroll
    for (int a = 0; a < 4; a++)
        #pragma unroll
        for (int b = 0; b < 8; b++)
            #pragma unroll
            for (int c = 0; c < 4; c++) d[a][b][c] = 0.0f;

    // ldmatrix lane mappings
    const int lm_row = (lane & 15);
    const int lm_hi  = (lane >> 4) & 1;
    const int lb_row = ((lane >> 4) & 1) * 8 + (lane & 7);
    const int lb_seg = (lane >> 3) & 1;

    const __half* Ag0 = A + (size_t)m0 * KP;
    const __half* Bg0 = B + (size_t)n0 * KP;

    // Prologue: chunks 0..1 into stages 0..1
    #pragma unroll
    for (int c = 0; c < STAGES - 1; c++) {
        load_chunk(smb + (SM_A_OFF + c * STAGE_ELEMS) * 2,
                   smb + (SM_B_OFF + c * STAGE_ELEMS) * 2,
                   Ag0 + c * BK, Bg0 + c * BK, tid);
        asm volatile("cp.async.commit_group;" ::: "memory");
    }

    int s = 0;
    for (int c = 0; c < NCH; c++) {
        if (c < NCH - 1) asm volatile("cp.async.wait_group 1;" ::: "memory");
        else             asm volatile("cp.async.wait_group 0;" ::: "memory");
        __syncthreads();

        // Prefetch chunk c+2 into stage (c+2)%3 (consumed at iter c-1;
        // the sync above ordered that compute before this write).
        if (c + STAGES - 1 < NCH) {
            int sp = s + (STAGES - 1); if (sp >= STAGES) sp -= STAGES;
            load_chunk(smb + (SM_A_OFF + sp * STAGE_ELEMS) * 2,
                       smb + (SM_B_OFF + sp * STAGE_ELEMS) * 2,
                       Ag0 + (c + STAGES - 1) * BK, Bg0 + (c + STAGES - 1) * BK, tid);
            asm volatile("cp.async.commit_group;" ::: "memory");
        }

        const uint32_t as = smb + (SM_A_OFF + s * STAGE_ELEMS) * 2;
        const uint32_t bs = smb + (SM_B_OFF + s * STAGE_ELEMS) * 2;

        #pragma unroll
        for (int ks = 0; ks < BK / 16; ks++) {
            uint32_t aF[4][4];
            #pragma unroll
            for (int mt = 0; mt < 4; mt++) {
                uint32_t addr = as + (((uint32_t)(wm + mt * 16 + lm_row) * ROWSTRIDE)
                                      + ks * 16 + lm_hi * 8) * 2;
                ldmatrix_x4(aF[mt][0], aF[mt][1], aF[mt][2], aF[mt][3], addr);
            }
            uint32_t bF[8][2];
            #pragma unroll
            for (int nt = 0; nt < 4; nt++) {
                uint32_t r0, r1, r2, r3;
                uint32_t addr = bs + (((uint32_t)(wn + nt * 16 + lb_row) * ROWSTRIDE)
                                      + ks * 16 + lb_seg * 8) * 2;
                ldmatrix_x4(r0, r1, r2, r3, addr);
                bF[nt * 2 + 0][0] = r0; bF[nt * 2 + 0][1] = r1;
                bF[nt * 2 + 1][0] = r2; bF[nt * 2 + 1][1] = r3;
            }
            #pragma unroll
            for (int mt = 0; mt < 4; mt++)
                #pragma unroll
                for (int nt = 0; nt < 8; nt++)
                    mma_f16(d[mt][nt][0], d[mt][nt][1], d[mt][nt][2], d[mt][nt][3],
                            aF[mt][0], aF[mt][1], aF[mt][2], aF[mt][3],
                            bF[nt][0], bF[nt][1]);
        }
        if (++s >= STAGES) s = 0;
    }

    // Epilogue: +bias, q14, store.
    #pragma unroll
    for (int mt = 0; mt < 4; mt++) {
        int r0 = m0 + wm + mt * 16 + g;
        int r1 = r0 + 8;
        #pragma unroll
        for (int nt = 0; nt < 8; nt++) {
            int cl = wn + nt * 8 + tq * 2;
            float b0 = sb_bias[cl], b1 = sb_bias[cl + 1];
            float2 o0, o1;
            o0.x = qround(d[mt][nt][0] + b0, S14F, I14F);
            o0.y = qround(d[mt][nt][1] + b1, S14F, I14F);
            o1.x = qround(d[mt][nt][2] + b0, S14F, I14F);
            o1.y = qround(d[mt][nt][3] + b1, S14F, I14F);
            *reinterpret_cast<float2*>(C + (size_t)r0 * N_DIM + n0 + cl) = o0;
            *reinterpret_cast<float2*>(C + (size_t)r1 * N_DIM + n0 + cl) = o1;
        }
    }
}

// ---------------------------------------------------------------------------
// Fused gate epilogue over [B, H], float4-vectorized.
// ---------------------------------------------------------------------------
__global__ __launch_bounds__(256)
void qgru_epilogue(const float* __restrict__ hidden, float* __restrict__ out)
{
    int idx = blockIdx.x * blockDim.x + threadIdx.x;
    if (idx >= (M_DIM * H_DIM) / 4) return;
    int b = idx >> 7;
    int h = (idx & 127) << 2;

    const float* gib = g_gi + (size_t)b * N_DIM;
    const float* ghb = g_gh + (size_t)b * N_DIM;

    float4 ir = *reinterpret_cast<const float4*>(gib + h);
    float4 ii = *reinterpret_cast<const float4*>(gib + h + H_DIM);
    float4 in_ = *reinterpret_cast<const float4*>(gib + h + 2 * H_DIM);
    float4 hr = *reinterpret_cast<const float4*>(ghb + h);
    float4 hi = *reinterpret_cast<const float4*>(ghb + h + H_DIM);
    float4 hn = *reinterpret_cast<const float4*>(ghb + h + 2 * H_DIM);
    float4 hd = *reinterpret_cast<const float4*>(hidden + (size_t)b * H_DIM + h);

    float irA[4] = {ir.x, ir.y, ir.z, ir.w};
    float iiA[4] = {ii.x, ii.y, ii.z, ii.w};
    float inA[4] = {in_.x, in_.y, in_.z, in_.w};
    float hrA[4] = {hr.x, hr.y, hr.z, hr.w};
    float hiA[4] = {hi.x, hi.y, hi.z, hi.w};
    float hnA[4] = {hn.x, hn.y, hn.z, hn.w};
    float hdA[4] = {hd.x, hd.y, hd.z, hd.w};
    float res[4];

    #pragma unroll
    for (int l = 0; l < 4; l++) {
        float rg  = qsig(__fadd_rn(irA[l], hrA[l]));
        float ig  = qsig(__fadd_rn(iiA[l], hiA[l]));
        float hnq = qround(hnA[l], Q27F, IQ27F);
        float rh  = qround(__fmul_rn(rg, hnq), S15F, I15F);
        float ng  = qtanhf_(__fadd_rn(rh, inA[l]));
        float nh  = qround(hdA[l], S15F, I15F);
        res[l] = __fadd_rn(ng, __fmul_rn(ig, __fsub_rn(nh, ng)));
    }

    float4 o = {res[0], res[1], res[2], res[3]};
    *reinterpret_cast<float4*>(out + (size_t)b * H_DIM + h) = o;
}

// ---------------------------------------------------------------------------
extern "C" void kernel_launch(void* const* d_in, const int* in_sizes, int n_in,
                              void* d_out, int out_size)
{
    const float* x   = (const float*)d_in[0];
    const float* h   = (const float*)d_in[1];
    const float* wih = (const float*)d_in[2];
    const float* whh = (const float*)d_in[3];
    const float* bih = (const float*)d_in[4];
    const float* bhh = (const float*)d_in[5];
    float* out = (float*)d_out;

    cudaFuncSetAttribute(gemm_mma, cudaFuncAttributeMaxDynamicSharedMemorySize,
                         GSMEM_BYTES);

    split_pack_all<<<(NSPLIT4 + 255) / 256, 256>>>(x, h, wih, whh);

    dim3 grid(N_DIM / TILE_N, M_DIM / TILE_M, 2);   // (12, 64, 2)
    gemm_mma<<<grid, 128, GSMEM_BYTES>>>(bih, bhh);

    int total = (M_DIM * H_DIM) / 4;
    qgru_epilogue<<<(total + 255) / 256, 256>>>(h, out);
}